// round 7
// baseline (speedup 1.0000x reference)
#include <cuda_runtime.h>
#include <cuda_fp16.h>
#include <cstdint>

// ---------------------------------------------------------------------------
// Problem constants
// ---------------------------------------------------------------------------
#define B_    4096
#define F_    784
#define D_    10000
#define C_    10
#define NW    313            // ceil(D/32) packed centroid words per class

// Single fp16 GEMM: A = fp16(x-0.5) [B_, 800], B = fp16(w) [NPAD, 800].
// Residual (quantization of both sides) has dot-rms ~9e-4 -> sign-flip rate
// ~1.6e-4/elem -> rel_err ~2-3e-4 (calibrated against round-4 measurement).
#define KPK   800
#define KSEG  784
#define NPAD  10240          // 40 * 256

// Tiling
#define TM      128
#define TN      256
#define BK      32           // fp16 elems per K-chunk
#define NCHUNK  (KPK / BK)   // 25
#define THREADS 512
#define STAGES  3

// Padded smem rows: 32 fp16 (64B) + 16B pad = 80B (conflict-free for ldmatrix)
#define RSB         80
#define A_ROWS      TM
#define BROWS       TN
#define STAGE_BYTES ((A_ROWS + BROWS) * RSB)     // 30720
#define SMEM_BYTES  (STAGES * STAGE_BYTES)       // 92160

// ---------------------------------------------------------------------------
// Device scratch (allocation-free: __device__ globals)
// ---------------------------------------------------------------------------
__device__ unsigned g_centPacked[C_ * NW];
__device__ __align__(16) __half g_Asp[(size_t)B_ * KPK];     // 6.6 MB
__device__ __align__(16) __half g_Bsp[(size_t)NPAD * KPK];   // 16.4 MB

// ---------------------------------------------------------------------------
// PTX helpers (sm_100 baseline: cp.async + ldmatrix + mma.sync only)
// ---------------------------------------------------------------------------
__device__ __forceinline__ uint32_t smem_u32(const void* p) {
    uint32_t a;
    asm("{ .reg .u64 t; cvta.to.shared.u64 t, %1; cvt.u32.u64 %0, t; }"
        : "=r"(a) : "l"(p));
    return a;
}

#define CP_ASYNC16(dst, src) \
    asm volatile("cp.async.cg.shared.global [%0], [%1], 16;" \
                 :: "r"(dst), "l"(src) : "memory")
#define CP_COMMIT() asm volatile("cp.async.commit_group;" ::: "memory")
#define CP_WAIT1()  asm volatile("cp.async.wait_group 1;" ::: "memory")
#define CP_WAIT0()  asm volatile("cp.async.wait_group 0;" ::: "memory")

#define LDMATRIX_X4(r0, r1, r2, r3, addr)                                     \
    asm volatile("ldmatrix.sync.aligned.m8n8.x4.shared.b16 {%0,%1,%2,%3}, [%4];" \
                 : "=r"(r0), "=r"(r1), "=r"(r2), "=r"(r3) : "r"(addr))

#define MMA16816(d0, d1, d2, d3, a0, a1, a2, a3, b0, b1)                      \
    asm volatile("mma.sync.aligned.m16n8k16.row.col.f32.f16.f16.f32 "         \
                 "{%0,%1,%2,%3}, {%4,%5,%6,%7}, {%8,%9}, {%0,%1,%2,%3};"      \
                 : "+f"(d0), "+f"(d1), "+f"(d2), "+f"(d3)                     \
                 : "r"(a0), "r"(a1), "r"(a2), "r"(a3), "r"(b0), "r"(b1))

// ---------------------------------------------------------------------------
// Prep kernels
// ---------------------------------------------------------------------------
__global__ void prep_A_kernel(const float* __restrict__ samples) {
    size_t idx = (size_t)blockIdx.x * blockDim.x + threadIdx.x;
    if (idx >= (size_t)B_ * KPK) return;
    int r = (int)(idx / KPK), f = (int)(idx % KPK);
    __half v = __float2half_rn(0.0f);
    if (f < KSEG)
        v = __float2half_rn(samples[(size_t)r * F_ + f] - 0.5f);
    g_Asp[idx] = v;
}

__global__ void prep_B_kernel(const float* __restrict__ bhv) {
    size_t idx = (size_t)blockIdx.x * blockDim.x + threadIdx.x;
    if (idx >= (size_t)NPAD * KPK) return;
    int r = (int)(idx / KPK), f = (int)(idx % KPK);
    __half v = __float2half_rn(0.0f);
    if (r < D_ && f < KSEG)
        v = __float2half_rn(bhv[(size_t)r * F_ + f]);
    g_Bsp[idx] = v;
}

__global__ void pack_centroids_kernel(const float* __restrict__ cent) {
    int idx = blockIdx.x * blockDim.x + threadIdx.x;
    if (idx >= C_ * NW) return;
    int c = idx / NW, w = idx % NW, d0 = w * 32;
    unsigned word = 0u;
    #pragma unroll
    for (int b = 0; b < 32; b++) {
        int d = d0 + b;
        if (d < D_ && cent[(size_t)c * D_ + d] > 0.5f) word |= (1u << b);
    }
    g_centPacked[idx] = word;
}

__global__ void zero_out_kernel(float* __restrict__ out) {
    int i = blockIdx.x * blockDim.x + threadIdx.x;
    if (i < B_ * C_) out[i] = 0.0f;
}

// ---------------------------------------------------------------------------
// Main kernel: fp16 mma.sync GEMM (M=128, N=256 per CTA, K=800) with fused
// sign-binarize / XOR-popcount / per-class Hamming epilogue.
// 16 warps: warpM = wid/4 (4 x 32 rows), warpN = wid%4 (4 x 64 cols).
// ---------------------------------------------------------------------------
__global__ void __launch_bounds__(THREADS, 1)
hdc_mma_kernel(float* __restrict__ out) {
    extern __shared__ char smem[];
    const uint32_t sbase = smem_u32(smem);
    const int tid   = threadIdx.x;
    const int wid   = tid >> 5;
    const int lane  = tid & 31;
    const int warpM = wid >> 2;
    const int warpN = wid & 3;
    const int bm = blockIdx.y * TM;
    const int bn = blockIdx.x * TN;

    const char* Abase = (const char*)(g_Asp + (size_t)bm * KPK);
    const char* Bbase = (const char*)(g_Bsp + (size_t)bn * KPK);

    float acc[2][8][4];
    #pragma unroll
    for (int i = 0; i < 2; i++)
        #pragma unroll
        for (int j = 0; j < 8; j++)
            #pragma unroll
            for (int e = 0; e < 4; e++)
                acc[i][j][e] = 0.0f;

    // ---- cp.async chunk loader: 1536 x 16B granules, 3 per thread ----
    auto load_chunk = [&](int c, int s) {
        uint32_t stage = sbase + s * STAGE_BYTES;
        #pragma unroll
        for (int i = 0; i < 3; i++) {
            int g   = tid + THREADS * i;       // 0..1535
            int row = g >> 2;
            int seg = g & 3;
            if (row < A_ROWS) {
                CP_ASYNC16(stage + row * RSB + seg * 16,
                           Abase + (size_t)row * (KPK * 2) + c * (BK * 2) + seg * 16);
            } else {
                int r2 = row - A_ROWS;
                CP_ASYNC16(stage + A_ROWS * RSB + r2 * RSB + seg * 16,
                           Bbase + (size_t)r2 * (KPK * 2) + c * (BK * 2) + seg * 16);
            }
        }
    };

    // ---- prologue: fill STAGES-1 stages ----
    #pragma unroll
    for (int p = 0; p < STAGES - 1; p++) {
        load_chunk(p, p);
        CP_COMMIT();
    }

    // ldmatrix base addresses (per warp)
    const uint32_t aRowSel = (lane & 15);
    const uint32_t aKByte  = (lane >> 4) * 16;
    const uint32_t bRowSel = ((lane >> 4) << 3) + (lane & 7);
    const uint32_t bKByte  = ((lane >> 3) & 1) * 16;

    for (int c = 0; c < NCHUNK; c++) {
        int s = c % STAGES;
        if (c + 1 < NCHUNK) CP_WAIT1(); else CP_WAIT0();
        __syncthreads();

        int cn = c + STAGES - 1;
        if (cn < NCHUNK) {
            load_chunk(cn, cn % STAGES);
            CP_COMMIT();
        }

        uint32_t sA = sbase + s * STAGE_BYTES + (warpM * 32) * RSB;
        uint32_t sB = sbase + s * STAGE_BYTES + A_ROWS * RSB + (warpN * 64) * RSB;

        #pragma unroll
        for (int ks = 0; ks < 2; ks++) {
            uint32_t a[2][4];
            #pragma unroll
            for (int i = 0; i < 2; i++) {
                uint32_t addr = sA + (i * 16 + aRowSel) * RSB + ks * 32 + aKByte;
                LDMATRIX_X4(a[i][0], a[i][1], a[i][2], a[i][3], addr);
            }
            uint32_t b[4][4];
            #pragma unroll
            for (int jj = 0; jj < 4; jj++) {
                uint32_t addr = sB + (jj * 16 + bRowSel) * RSB + ks * 32 + bKByte;
                LDMATRIX_X4(b[jj][0], b[jj][1], b[jj][2], b[jj][3], addr);
            }
            #pragma unroll
            for (int i = 0; i < 2; i++)
                #pragma unroll
                for (int jj = 0; jj < 4; jj++) {
                    MMA16816(acc[i][2*jj][0], acc[i][2*jj][1], acc[i][2*jj][2], acc[i][2*jj][3],
                             a[i][0], a[i][1], a[i][2], a[i][3], b[jj][0], b[jj][1]);
                    MMA16816(acc[i][2*jj+1][0], acc[i][2*jj+1][1], acc[i][2*jj+1][2], acc[i][2*jj+1][3],
                             a[i][0], a[i][1], a[i][2], a[i][3], b[jj][2], b[jj][3]);
                }
        }
    }

    // =======================================================================
    // Epilogue
    // =======================================================================
    __syncthreads();   // stage buffers free -> reuse as sign board (128x256 bytes)

    // Phase 1: dump sign bytes. signs[row][col] at smem offset row*256+col.
    {
        int rbase = warpM * 32 + (lane >> 2);
        int cbase = warpN * 64 + ((lane & 3) << 1);
        #pragma unroll
        for (int i = 0; i < 2; i++)
            #pragma unroll
            for (int j = 0; j < 8; j++)
                #pragma unroll
                for (int e = 0; e < 4; e++) {
                    int row = rbase + i * 16 + ((e >> 1) << 3);
                    int col = cbase + j * 8 + (e & 1);
                    smem[row * 256 + col] = (acc[i][j][e] > 0.0f) ? 1 : 0;
                }
    }
    __syncthreads();

    // Phase 2: pack 32 sign bytes -> word, XOR-popcount vs packed centroids.
    {
        int row = tid >> 2;
        int cnt[C_];
        #pragma unroll
        for (int c = 0; c < C_; c++) cnt[c] = 0;

        #pragma unroll
        for (int q = 0; q < 2; q++) {
            int w = ((tid & 3) << 1) + q;
            const uint32_t* p = (const uint32_t*)(smem + row * 256 + w * 32);
            unsigned word = 0u;
            #pragma unroll
            for (int x = 0; x < 8; x++) {
                unsigned nib = ((p[x] & 0x01010101u) * 0x01020408u) >> 24;
                word |= (nib & 0xFu) << (4 * x);
            }
            int dw = (bn >> 5) + w;
            if (dw < NW) {
                #pragma unroll
                for (int c = 0; c < C_; c++)
                    cnt[c] += __popc(word ^ g_centPacked[c * NW + dw]);
            }
        }
        #pragma unroll
        for (int c = 0; c < C_; c++) {
            cnt[c] += __shfl_xor_sync(0xFFFFFFFFu, cnt[c], 1);
            cnt[c] += __shfl_xor_sync(0xFFFFFFFFu, cnt[c], 2);
        }
        if ((lane & 3) == 0) {
            #pragma unroll
            for (int c = 0; c < C_; c++)
                atomicAdd(&out[(size_t)(bm + row) * C_ + c], -(float)cnt[c]);
        }
    }
}

// ---------------------------------------------------------------------------
extern "C" void kernel_launch(void* const* d_in, const int* in_sizes, int n_in,
                              void* d_out, int out_size) {
    const float* samples = (const float*)d_in[0];   // [4096, 784]
    const float* bhv     = (const float*)d_in[1];   // [10000, 784]
    const float* cent    = (const float*)d_in[2];   // [10, 10000]
    float* out = (float*)d_out;                     // [4096, 10]

    cudaFuncSetAttribute(hdc_mma_kernel,
                         cudaFuncAttributeMaxDynamicSharedMemorySize, SMEM_BYTES);

    {
        size_t n = (size_t)B_ * KPK;
        prep_A_kernel<<<(unsigned)((n + 255) / 256), 256>>>(samples);
    }
    {
        size_t n = (size_t)NPAD * KPK;
        prep_B_kernel<<<(unsigned)((n + 255) / 256), 256>>>(bhv);
    }
    pack_centroids_kernel<<<(C_ * NW + 255) / 256, 256>>>(cent);
    zero_out_kernel<<<(B_ * C_ + 255) / 256, 256>>>(out);

    dim3 grid(NPAD / TN, B_ / TM);   // (40, 32)
    hdc_mma_kernel<<<grid, THREADS, SMEM_BYTES>>>(out);
}

// round 8
// speedup vs baseline: 1.7645x; 1.7645x over previous
#include <cuda_runtime.h>
#include <cstdint>

// ---------------------------------------------------------------------------
// Problem constants
// ---------------------------------------------------------------------------
#define B_    4096
#define F_    784
#define D_    10000
#define C_    10
#define NW    313            // ceil(D/32) packed centroid words per class

// Single int8 GEMM: A = round(254*(x-0.5)) [B_, 800], B = round(127*w) [NPAD, 800].
// s32 accumulate is exact; sign(acc) = sign of the quantized dot. Quantization
// noise dot-rms ~2.6e-2 vs dot rms 4.7 -> flip rate ~2.2e-3 -> rel_err ~5e-4
// (flip model calibrated 1.4-2x conservative across rounds 3/4/7).
#define KPK   800
#define KSEG  784
#define NPAD  10240          // 40 * 256

// Tiling
#define TM      128
#define TN      256
#define BK      32           // int8 elems (bytes) per K-chunk
#define NCHUNK  (KPK / BK)   // 25
#define THREADS 512
#define STAGES  3

// Padded smem rows: 32B data + 16B pad = 48B.
// Row offsets mod 128B = {0,48,96,16,64,112,32,80}: 8 distinct 16B lanes
// covering all 32 banks -> ldmatrix conflict-free.
#define RSB         48
#define A_ROWS      TM
#define BROWS       TN
#define STAGE_BYTES ((A_ROWS + BROWS) * RSB)     // 18432
#define SMEM_BYTES  (STAGES * STAGE_BYTES)       // 55296 (epilogue board 32KB fits)

// ---------------------------------------------------------------------------
// Device scratch (allocation-free: __device__ globals)
// ---------------------------------------------------------------------------
__device__ unsigned g_centPacked[C_ * NW];
__device__ __align__(16) signed char g_Asp[(size_t)B_ * KPK];     // 3.3 MB
__device__ __align__(16) signed char g_Bsp[(size_t)NPAD * KPK];   // 8.2 MB

// ---------------------------------------------------------------------------
// PTX helpers (sm_100 baseline: cp.async + ldmatrix + mma.sync only)
// ---------------------------------------------------------------------------
__device__ __forceinline__ uint32_t smem_u32(const void* p) {
    uint32_t a;
    asm("{ .reg .u64 t; cvta.to.shared.u64 t, %1; cvt.u32.u64 %0, t; }"
        : "=r"(a) : "l"(p));
    return a;
}

#define CP_ASYNC16(dst, src) \
    asm volatile("cp.async.cg.shared.global [%0], [%1], 16;" \
                 :: "r"(dst), "l"(src) : "memory")
#define CP_COMMIT() asm volatile("cp.async.commit_group;" ::: "memory")
#define CP_WAIT1()  asm volatile("cp.async.wait_group 1;" ::: "memory")
#define CP_WAIT0()  asm volatile("cp.async.wait_group 0;" ::: "memory")

#define LDMATRIX_X4(r0, r1, r2, r3, addr)                                     \
    asm volatile("ldmatrix.sync.aligned.m8n8.x4.shared.b16 {%0,%1,%2,%3}, [%4];" \
                 : "=r"(r0), "=r"(r1), "=r"(r2), "=r"(r3) : "r"(addr))

// int8 IMMA: m16n8k32, s8 x s8 -> s32
#define IMMA16832(d0, d1, d2, d3, a0, a1, a2, a3, b0, b1)                     \
    asm volatile("mma.sync.aligned.m16n8k32.row.col.s32.s8.s8.s32 "           \
                 "{%0,%1,%2,%3}, {%4,%5,%6,%7}, {%8,%9}, {%0,%1,%2,%3};"      \
                 : "+r"(d0), "+r"(d1), "+r"(d2), "+r"(d3)                     \
                 : "r"(a0), "r"(a1), "r"(a2), "r"(a3), "r"(b0), "r"(b1))

// ---------------------------------------------------------------------------
// Prep kernels
// ---------------------------------------------------------------------------
__global__ void prep_A_kernel(const float* __restrict__ samples) {
    size_t idx = (size_t)blockIdx.x * blockDim.x + threadIdx.x;
    if (idx >= (size_t)B_ * KPK) return;
    int r = (int)(idx / KPK), f = (int)(idx % KPK);
    int v = 0;
    if (f < KSEG) {
        v = __float2int_rn(254.0f * (samples[(size_t)r * F_ + f] - 0.5f));
        v = max(-127, min(127, v));
    }
    g_Asp[idx] = (signed char)v;
}

__global__ void prep_B_kernel(const float* __restrict__ bhv) {
    size_t idx = (size_t)blockIdx.x * blockDim.x + threadIdx.x;
    if (idx >= (size_t)NPAD * KPK) return;
    int r = (int)(idx / KPK), f = (int)(idx % KPK);
    int v = 0;
    if (r < D_ && f < KSEG) {
        v = __float2int_rn(127.0f * bhv[(size_t)r * F_ + f]);
        v = max(-127, min(127, v));
    }
    g_Bsp[idx] = (signed char)v;
}

__global__ void pack_centroids_kernel(const float* __restrict__ cent) {
    int idx = blockIdx.x * blockDim.x + threadIdx.x;
    if (idx >= C_ * NW) return;
    int c = idx / NW, w = idx % NW, d0 = w * 32;
    unsigned word = 0u;
    #pragma unroll
    for (int b = 0; b < 32; b++) {
        int d = d0 + b;
        if (d < D_ && cent[(size_t)c * D_ + d] > 0.5f) word |= (1u << b);
    }
    g_centPacked[idx] = word;
}

__global__ void zero_out_kernel(float* __restrict__ out) {
    int i = blockIdx.x * blockDim.x + threadIdx.x;
    if (i < B_ * C_) out[i] = 0.0f;
}

// ---------------------------------------------------------------------------
// Main kernel: int8 mma.sync GEMM (M=128, N=256 per CTA, K=800) with fused
// sign-binarize / XOR-popcount / per-class Hamming epilogue.
// 16 warps: warpM = wid/4 (4 x 32 rows), warpN = wid%4 (4 x 64 cols).
// ---------------------------------------------------------------------------
__global__ void __launch_bounds__(THREADS, 1)
hdc_mma_kernel(float* __restrict__ out) {
    extern __shared__ char smem[];
    const uint32_t sbase = smem_u32(smem);
    const int tid   = threadIdx.x;
    const int wid   = tid >> 5;
    const int lane  = tid & 31;
    const int warpM = wid >> 2;
    const int warpN = wid & 3;
    const int bm = blockIdx.y * TM;
    const int bn = blockIdx.x * TN;

    const char* Abase = (const char*)(g_Asp + (size_t)bm * KPK);
    const char* Bbase = (const char*)(g_Bsp + (size_t)bn * KPK);

    int acc[2][8][4];
    #pragma unroll
    for (int i = 0; i < 2; i++)
        #pragma unroll
        for (int j = 0; j < 8; j++)
            #pragma unroll
            for (int e = 0; e < 4; e++)
                acc[i][j][e] = 0;

    // ---- cp.async chunk loader: 768 x 16B granules (384 rows x 2 halves) ----
    auto load_chunk = [&](int c, int s) {
        uint32_t stage = sbase + s * STAGE_BYTES;
        #pragma unroll
        for (int i = 0; i < 2; i++) {
            int g = tid + THREADS * i;         // 0..1023
            if (g < 768) {
                int row = g >> 1, h = g & 1;
                if (row < A_ROWS) {
                    CP_ASYNC16(stage + row * RSB + h * 16,
                               Abase + (size_t)row * KPK + c * BK + h * 16);
                } else {
                    int r2 = row - A_ROWS;
                    CP_ASYNC16(stage + A_ROWS * RSB + r2 * RSB + h * 16,
                               Bbase + (size_t)r2 * KPK + c * BK + h * 16);
                }
            }
        }
    };

    // ---- prologue: fill STAGES-1 stages ----
    #pragma unroll
    for (int p = 0; p < STAGES - 1; p++) {
        load_chunk(p, p);
        CP_COMMIT();
    }

    // ldmatrix address components (byte-coincident with s8-k32 MMA fragments):
    // A x4: lanes 0-7 rows 0-7 half0, 8-15 rows 8-15 half0,
    //       16-23 rows 0-7 half1, 24-31 rows 8-15 half1.
    // B x4: lanes 0-7 rows 0-7 half0, 8-15 rows 0-7 half1,
    //       16-23 rows 8-15 half0, 24-31 rows 8-15 half1.
    const uint32_t aRowSel = (lane & 15);
    const uint32_t aOff16  = (lane >> 4) * 16;
    const uint32_t bRowSel = ((lane >> 4) << 3) + (lane & 7);
    const uint32_t bOff16  = ((lane >> 3) & 1) * 16;

    for (int c = 0; c < NCHUNK; c++) {
        int s = c % STAGES;
        if (c + 1 < NCHUNK) CP_WAIT1(); else CP_WAIT0();
        __syncthreads();

        int cn = c + STAGES - 1;
        if (cn < NCHUNK) {
            load_chunk(cn, cn % STAGES);
            CP_COMMIT();
        }

        uint32_t sA = sbase + s * STAGE_BYTES + (warpM * 32) * RSB;
        uint32_t sB = sbase + s * STAGE_BYTES + A_ROWS * RSB + (warpN * 64) * RSB;

        uint32_t a[2][4];
        #pragma unroll
        for (int i = 0; i < 2; i++) {
            uint32_t addr = sA + (i * 16 + aRowSel) * RSB + aOff16;
            LDMATRIX_X4(a[i][0], a[i][1], a[i][2], a[i][3], addr);
        }
        uint32_t b[4][4];
        #pragma unroll
        for (int jj = 0; jj < 4; jj++) {
            uint32_t addr = sB + (jj * 16 + bRowSel) * RSB + bOff16;
            LDMATRIX_X4(b[jj][0], b[jj][1], b[jj][2], b[jj][3], addr);
        }
        #pragma unroll
        for (int i = 0; i < 2; i++)
            #pragma unroll
            for (int jj = 0; jj < 4; jj++) {
                IMMA16832(acc[i][2*jj][0], acc[i][2*jj][1], acc[i][2*jj][2], acc[i][2*jj][3],
                          a[i][0], a[i][1], a[i][2], a[i][3], b[jj][0], b[jj][1]);
                IMMA16832(acc[i][2*jj+1][0], acc[i][2*jj+1][1], acc[i][2*jj+1][2], acc[i][2*jj+1][3],
                          a[i][0], a[i][1], a[i][2], a[i][3], b[jj][2], b[jj][3]);
            }
    }

    // =======================================================================
    // Epilogue (fragment layout of s32 C identical to f32 C)
    // =======================================================================
    __syncthreads();   // stage buffers free -> reuse as sign board (128x256 bytes)

    // Phase 1: dump sign bytes. signs[row][col] at smem offset row*256+col.
    {
        int rbase = warpM * 32 + (lane >> 2);
        int cbase = warpN * 64 + ((lane & 3) << 1);
        #pragma unroll
        for (int i = 0; i < 2; i++)
            #pragma unroll
            for (int j = 0; j < 8; j++)
                #pragma unroll
                for (int e = 0; e < 4; e++) {
                    int row = rbase + i * 16 + ((e >> 1) << 3);
                    int col = cbase + j * 8 + (e & 1);
                    smem[row * 256 + col] = (acc[i][j][e] > 0) ? 1 : 0;
                }
    }
    __syncthreads();

    // Phase 2: pack 32 sign bytes -> word, XOR-popcount vs packed centroids.
    {
        int row = tid >> 2;
        int cnt[C_];
        #pragma unroll
        for (int c = 0; c < C_; c++) cnt[c] = 0;

        #pragma unroll
        for (int q = 0; q < 2; q++) {
            int w = ((tid & 3) << 1) + q;
            const uint32_t* p = (const uint32_t*)(smem + row * 256 + w * 32);
            unsigned word = 0u;
            #pragma unroll
            for (int x = 0; x < 8; x++) {
                unsigned nib = ((p[x] & 0x01010101u) * 0x01020408u) >> 24;
                word |= (nib & 0xFu) << (4 * x);
            }
            int dw = (bn >> 5) + w;
            if (dw < NW) {
                #pragma unroll
                for (int c = 0; c < C_; c++)
                    cnt[c] += __popc(word ^ g_centPacked[c * NW + dw]);
            }
        }
        #pragma unroll
        for (int c = 0; c < C_; c++) {
            cnt[c] += __shfl_xor_sync(0xFFFFFFFFu, cnt[c], 1);
            cnt[c] += __shfl_xor_sync(0xFFFFFFFFu, cnt[c], 2);
        }
        if ((lane & 3) == 0) {
            #pragma unroll
            for (int c = 0; c < C_; c++)
                atomicAdd(&out[(size_t)(bm + row) * C_ + c], -(float)cnt[c]);
        }
    }
}

// ---------------------------------------------------------------------------
extern "C" void kernel_launch(void* const* d_in, const int* in_sizes, int n_in,
                              void* d_out, int out_size) {
    const float* samples = (const float*)d_in[0];   // [4096, 784]
    const float* bhv     = (const float*)d_in[1];   // [10000, 784]
    const float* cent    = (const float*)d_in[2];   // [10, 10000]
    float* out = (float*)d_out;                     // [4096, 10]

    cudaFuncSetAttribute(hdc_mma_kernel,
                         cudaFuncAttributeMaxDynamicSharedMemorySize, SMEM_BYTES);

    {
        size_t n = (size_t)B_ * KPK;
        prep_A_kernel<<<(unsigned)((n + 255) / 256), 256>>>(samples);
    }
    {
        size_t n = (size_t)NPAD * KPK;
        prep_B_kernel<<<(unsigned)((n + 255) / 256), 256>>>(bhv);
    }
    pack_centroids_kernel<<<(C_ * NW + 255) / 256, 256>>>(cent);
    zero_out_kernel<<<(B_ * C_ + 255) / 256, 256>>>(out);

    dim3 grid(NPAD / TN, B_ / TM);   // (40, 32)
    hdc_mma_kernel<<<grid, THREADS, SMEM_BYTES>>>(out);
}

// round 9
// speedup vs baseline: 1.7680x; 1.0020x over previous
#include <cuda_runtime.h>
#include <cstdint>

// ---------------------------------------------------------------------------
// Problem constants
// ---------------------------------------------------------------------------
#define B_    4096
#define F_    784
#define D_    10000
#define C_    10
#define NW    313            // ceil(D/32) packed centroid words per class

// Single int8 GEMM: A = round(254*(x-0.5)) [B_, 800], B = round(127*w) [NPAD, 800].
// s32 accumulate is exact; sign(acc) = sign of the quantized dot. Quantization
// noise dot-rms ~2.6e-2 vs dot rms 4.7 -> flip rate ~2.2e-3 -> rel_err ~5e-4
// (flip model calibrated 1.4-2x conservative across rounds 3/4/7).
#define KPK   800
#define KSEG  784
#define NPAD  10240          // 40 * 256

// Tiling
#define TM      128
#define TN      256
#define BK      32           // int8 elems (bytes) per K-chunk
#define NCHUNK  (KPK / BK)   // 25
#define THREADS 512
#define STAGES  3

// Padded smem rows: 32B data + 16B pad = 48B.
// Row offsets mod 128B = {0,48,96,16,64,112,32,80}: 8 distinct 16B lanes
// covering all 32 banks -> ldmatrix conflict-free.
#define RSB         48
#define A_ROWS      TM
#define BROWS       TN
#define STAGE_BYTES ((A_ROWS + BROWS) * RSB)     // 18432
#define SMEM_BYTES  (STAGES * STAGE_BYTES)       // 55296 (epilogue board 32KB fits)

// ---------------------------------------------------------------------------
// Device scratch (allocation-free: __device__ globals)
// ---------------------------------------------------------------------------
__device__ unsigned g_centPacked[C_ * NW];
__device__ __align__(16) signed char g_Asp[(size_t)B_ * KPK];     // 3.3 MB
__device__ __align__(16) signed char g_Bsp[(size_t)NPAD * KPK];   // 8.2 MB

// ---------------------------------------------------------------------------
// PTX helpers (sm_100 baseline: cp.async + ldmatrix + mma.sync only)
// ---------------------------------------------------------------------------
__device__ __forceinline__ uint32_t smem_u32(const void* p) {
    uint32_t a;
    asm("{ .reg .u64 t; cvta.to.shared.u64 t, %1; cvt.u32.u64 %0, t; }"
        : "=r"(a) : "l"(p));
    return a;
}

#define CP_ASYNC16(dst, src) \
    asm volatile("cp.async.cg.shared.global [%0], [%1], 16;" \
                 :: "r"(dst), "l"(src) : "memory")
#define CP_COMMIT() asm volatile("cp.async.commit_group;" ::: "memory")
#define CP_WAIT1()  asm volatile("cp.async.wait_group 1;" ::: "memory")
#define CP_WAIT0()  asm volatile("cp.async.wait_group 0;" ::: "memory")

#define LDMATRIX_X4(r0, r1, r2, r3, addr)                                     \
    asm volatile("ldmatrix.sync.aligned.m8n8.x4.shared.b16 {%0,%1,%2,%3}, [%4];" \
                 : "=r"(r0), "=r"(r1), "=r"(r2), "=r"(r3) : "r"(addr))

// int8 IMMA: m16n8k32, s8 x s8 -> s32
#define IMMA16832(d0, d1, d2, d3, a0, a1, a2, a3, b0, b1)                     \
    asm volatile("mma.sync.aligned.m16n8k32.row.col.s32.s8.s8.s32 "           \
                 "{%0,%1,%2,%3}, {%4,%5,%6,%7}, {%8,%9}, {%0,%1,%2,%3};"      \
                 : "+r"(d0), "+r"(d1), "+r"(d2), "+r"(d3)                     \
                 : "r"(a0), "r"(a1), "r"(a2), "r"(a3), "r"(b0), "r"(b1))

// ---------------------------------------------------------------------------
// Prep kernels
// ---------------------------------------------------------------------------
__global__ void prep_A_kernel(const float* __restrict__ samples) {
    size_t idx = (size_t)blockIdx.x * blockDim.x + threadIdx.x;
    if (idx >= (size_t)B_ * KPK) return;
    int r = (int)(idx / KPK), f = (int)(idx % KPK);
    int v = 0;
    if (f < KSEG) {
        v = __float2int_rn(254.0f * (samples[(size_t)r * F_ + f] - 0.5f));
        v = max(-127, min(127, v));
    }
    g_Asp[idx] = (signed char)v;
}

__global__ void prep_B_kernel(const float* __restrict__ bhv) {
    size_t idx = (size_t)blockIdx.x * blockDim.x + threadIdx.x;
    if (idx >= (size_t)NPAD * KPK) return;
    int r = (int)(idx / KPK), f = (int)(idx % KPK);
    int v = 0;
    if (r < D_ && f < KSEG) {
        v = __float2int_rn(127.0f * bhv[(size_t)r * F_ + f]);
        v = max(-127, min(127, v));
    }
    g_Bsp[idx] = (signed char)v;
}

__global__ void pack_centroids_kernel(const float* __restrict__ cent) {
    int idx = blockIdx.x * blockDim.x + threadIdx.x;
    if (idx >= C_ * NW) return;
    int c = idx / NW, w = idx % NW, d0 = w * 32;
    unsigned word = 0u;
    #pragma unroll
    for (int b = 0; b < 32; b++) {
        int d = d0 + b;
        if (d < D_ && cent[(size_t)c * D_ + d] > 0.5f) word |= (1u << b);
    }
    g_centPacked[idx] = word;
}

__global__ void zero_out_kernel(float* __restrict__ out) {
    int i = blockIdx.x * blockDim.x + threadIdx.x;
    if (i < B_ * C_) out[i] = 0.0f;
}

// ---------------------------------------------------------------------------
// Main kernel: int8 mma.sync GEMM (M=128, N=256 per CTA, K=800) with fused
// sign-binarize / XOR-popcount / per-class Hamming epilogue.
// 16 warps: warpM = wid/4 (4 x 32 rows), warpN = wid%4 (4 x 64 cols).
// ---------------------------------------------------------------------------
__global__ void __launch_bounds__(THREADS, 1)
hdc_mma_kernel(float* __restrict__ out) {
    extern __shared__ char smem[];
    const uint32_t sbase = smem_u32(smem);
    const int tid   = threadIdx.x;
    const int wid   = tid >> 5;
    const int lane  = tid & 31;
    const int warpM = wid >> 2;
    const int warpN = wid & 3;
    const int bm = blockIdx.y * TM;
    const int bn = blockIdx.x * TN;

    const char* Abase = (const char*)(g_Asp + (size_t)bm * KPK);
    const char* Bbase = (const char*)(g_Bsp + (size_t)bn * KPK);

    int acc[2][8][4];
    #pragma unroll
    for (int i = 0; i < 2; i++)
        #pragma unroll
        for (int j = 0; j < 8; j++)
            #pragma unroll
            for (int e = 0; e < 4; e++)
                acc[i][j][e] = 0;

    // ---- cp.async chunk loader: 768 x 16B granules (384 rows x 2 halves) ----
    auto load_chunk = [&](int c, int s) {
        uint32_t stage = sbase + s * STAGE_BYTES;
        #pragma unroll
        for (int i = 0; i < 2; i++) {
            int g = tid + THREADS * i;         // 0..1023
            if (g < 768) {
                int row = g >> 1, h = g & 1;
                if (row < A_ROWS) {
                    CP_ASYNC16(stage + row * RSB + h * 16,
                               Abase + (size_t)row * KPK + c * BK + h * 16);
                } else {
                    int r2 = row - A_ROWS;
                    CP_ASYNC16(stage + A_ROWS * RSB + r2 * RSB + h * 16,
                               Bbase + (size_t)r2 * KPK + c * BK + h * 16);
                }
            }
        }
    };

    // ---- prologue: fill STAGES-1 stages ----
    #pragma unroll
    for (int p = 0; p < STAGES - 1; p++) {
        load_chunk(p, p);
        CP_COMMIT();
    }

    // ldmatrix address components (byte-coincident with s8-k32 MMA fragments):
    // A x4: lanes 0-7 rows 0-7 half0, 8-15 rows 8-15 half0,
    //       16-23 rows 0-7 half1, 24-31 rows 8-15 half1.
    // B x4: lanes 0-7 rows 0-7 half0, 8-15 rows 0-7 half1,
    //       16-23 rows 8-15 half0, 24-31 rows 8-15 half1.
    const uint32_t aRowSel = (lane & 15);
    const uint32_t aOff16  = (lane >> 4) * 16;
    const uint32_t bRowSel = ((lane >> 4) << 3) + (lane & 7);
    const uint32_t bOff16  = ((lane >> 3) & 1) * 16;

    for (int c = 0; c < NCHUNK; c++) {
        int s = c % STAGES;
        if (c + 1 < NCHUNK) CP_WAIT1(); else CP_WAIT0();
        __syncthreads();

        int cn = c + STAGES - 1;
        if (cn < NCHUNK) {
            load_chunk(cn, cn % STAGES);
            CP_COMMIT();
        }

        uint32_t sA = sbase + s * STAGE_BYTES + (warpM * 32) * RSB;
        uint32_t sB = sbase + s * STAGE_BYTES + A_ROWS * RSB + (warpN * 64) * RSB;

        uint32_t a[2][4];
        #pragma unroll
        for (int i = 0; i < 2; i++) {
            uint32_t addr = sA + (i * 16 + aRowSel) * RSB + aOff16;
            LDMATRIX_X4(a[i][0], a[i][1], a[i][2], a[i][3], addr);
        }
        uint32_t b[4][4];
        #pragma unroll
        for (int jj = 0; jj < 4; jj++) {
            uint32_t addr = sB + (jj * 16 + bRowSel) * RSB + bOff16;
            LDMATRIX_X4(b[jj][0], b[jj][1], b[jj][2], b[jj][3], addr);
        }
        #pragma unroll
        for (int i = 0; i < 2; i++)
            #pragma unroll
            for (int jj = 0; jj < 4; jj++) {
                IMMA16832(acc[i][2*jj][0], acc[i][2*jj][1], acc[i][2*jj][2], acc[i][2*jj][3],
                          a[i][0], a[i][1], a[i][2], a[i][3], b[jj][0], b[jj][1]);
                IMMA16832(acc[i][2*jj+1][0], acc[i][2*jj+1][1], acc[i][2*jj+1][2], acc[i][2*jj+1][3],
                          a[i][0], a[i][1], a[i][2], a[i][3], b[jj][2], b[jj][3]);
            }
    }

    // =======================================================================
    // Epilogue (fragment layout of s32 C identical to f32 C)
    // =======================================================================
    __syncthreads();   // stage buffers free -> reuse as sign board (128x256 bytes)

    // Phase 1: dump sign bytes. signs[row][col] at smem offset row*256+col.
    {
        int rbase = warpM * 32 + (lane >> 2);
        int cbase = warpN * 64 + ((lane & 3) << 1);
        #pragma unroll
        for (int i = 0; i < 2; i++)
            #pragma unroll
            for (int j = 0; j < 8; j++)
                #pragma unroll
                for (int e = 0; e < 4; e++) {
                    int row = rbase + i * 16 + ((e >> 1) << 3);
                    int col = cbase + j * 8 + (e & 1);
                    smem[row * 256 + col] = (acc[i][j][e] > 0) ? 1 : 0;
                }
    }
    __syncthreads();

    // Phase 2: pack 32 sign bytes -> word, XOR-popcount vs packed centroids.
    {
        int row = tid >> 2;
        int cnt[C_];
        #pragma unroll
        for (int c = 0; c < C_; c++) cnt[c] = 0;

        #pragma unroll
        for (int q = 0; q < 2; q++) {
            int w = ((tid & 3) << 1) + q;
            const uint32_t* p = (const uint32_t*)(smem + row * 256 + w * 32);
            unsigned word = 0u;
            #pragma unroll
            for (int x = 0; x < 8; x++) {
                unsigned nib = ((p[x] & 0x01010101u) * 0x01020408u) >> 24;
                word |= (nib & 0xFu) << (4 * x);
            }
            int dw = (bn >> 5) + w;
            if (dw < NW) {
                #pragma unroll
                for (int c = 0; c < C_; c++)
                    cnt[c] += __popc(word ^ g_centPacked[c * NW + dw]);
            }
        }
        #pragma unroll
        for (int c = 0; c < C_; c++) {
            cnt[c] += __shfl_xor_sync(0xFFFFFFFFu, cnt[c], 1);
            cnt[c] += __shfl_xor_sync(0xFFFFFFFFu, cnt[c], 2);
        }
        if ((lane & 3) == 0) {
            #pragma unroll
            for (int c = 0; c < C_; c++)
                atomicAdd(&out[(size_t)(bm + row) * C_ + c], -(float)cnt[c]);
        }
    }
}

// ---------------------------------------------------------------------------
extern "C" void kernel_launch(void* const* d_in, const int* in_sizes, int n_in,
                              void* d_out, int out_size) {
    const float* samples = (const float*)d_in[0];   // [4096, 784]
    const float* bhv     = (const float*)d_in[1];   // [10000, 784]
    const float* cent    = (const float*)d_in[2];   // [10, 10000]
    float* out = (float*)d_out;                     // [4096, 10]

    cudaFuncSetAttribute(hdc_mma_kernel,
                         cudaFuncAttributeMaxDynamicSharedMemorySize, SMEM_BYTES);

    {
        size_t n = (size_t)B_ * KPK;
        prep_A_kernel<<<(unsigned)((n + 255) / 256), 256>>>(samples);
    }
    {
        size_t n = (size_t)NPAD * KPK;
        prep_B_kernel<<<(unsigned)((n + 255) / 256), 256>>>(bhv);
    }
    pack_centroids_kernel<<<(C_ * NW + 255) / 256, 256>>>(cent);
    zero_out_kernel<<<(B_ * C_ + 255) / 256, 256>>>(out);

    dim3 grid(NPAD / TN, B_ / TM);   // (40, 32)
    hdc_mma_kernel<<<grid, THREADS, SMEM_BYTES>>>(out);
}

// round 10
// speedup vs baseline: 1.7683x; 1.0002x over previous
#include <cuda_runtime.h>
#include <cstdint>

// ---------------------------------------------------------------------------
// Problem constants
// ---------------------------------------------------------------------------
#define B_    4096
#define F_    784
#define D_    10000
#define C_    10
#define NW    313            // ceil(D/32) packed centroid words per class

// Single int8 GEMM: A = round(254*(x-0.5)) [B_, 800], B = round(127*w) [NPAD, 800].
// s32 accumulate is exact; sign(acc) = sign of the quantized dot. Quantization
// noise dot-rms ~2.6e-2 vs dot rms 4.7 -> flip rate ~2.2e-3 -> rel_err ~5e-4
// (flip model calibrated 1.4-2x conservative across rounds 3/4/7).
#define KPK   800
#define KSEG  784
#define NPAD  10240          // 40 * 256

// Tiling
#define TM      128
#define TN      256
#define BK      32           // int8 elems (bytes) per K-chunk
#define NCHUNK  (KPK / BK)   // 25
#define THREADS 512
#define STAGES  3

// Padded smem rows: 32B data + 16B pad = 48B.
// Row offsets mod 128B = {0,48,96,16,64,112,32,80}: 8 distinct 16B lanes
// covering all 32 banks -> ldmatrix conflict-free.
#define RSB         48
#define A_ROWS      TM
#define BROWS       TN
#define STAGE_BYTES ((A_ROWS + BROWS) * RSB)     // 18432
#define SMEM_BYTES  (STAGES * STAGE_BYTES)       // 55296 (epilogue board 32KB fits)

// ---------------------------------------------------------------------------
// Device scratch (allocation-free: __device__ globals)
// ---------------------------------------------------------------------------
__device__ unsigned g_centPacked[C_ * NW];
__device__ __align__(16) signed char g_Asp[(size_t)B_ * KPK];     // 3.3 MB
__device__ __align__(16) signed char g_Bsp[(size_t)NPAD * KPK];   // 8.2 MB

// ---------------------------------------------------------------------------
// PTX helpers (sm_100 baseline: cp.async + ldmatrix + mma.sync only)
// ---------------------------------------------------------------------------
__device__ __forceinline__ uint32_t smem_u32(const void* p) {
    uint32_t a;
    asm("{ .reg .u64 t; cvta.to.shared.u64 t, %1; cvt.u32.u64 %0, t; }"
        : "=r"(a) : "l"(p));
    return a;
}

#define CP_ASYNC16(dst, src) \
    asm volatile("cp.async.cg.shared.global [%0], [%1], 16;" \
                 :: "r"(dst), "l"(src) : "memory")
#define CP_COMMIT() asm volatile("cp.async.commit_group;" ::: "memory")
#define CP_WAIT1()  asm volatile("cp.async.wait_group 1;" ::: "memory")
#define CP_WAIT0()  asm volatile("cp.async.wait_group 0;" ::: "memory")

#define LDMATRIX_X4(r0, r1, r2, r3, addr)                                     \
    asm volatile("ldmatrix.sync.aligned.m8n8.x4.shared.b16 {%0,%1,%2,%3}, [%4];" \
                 : "=r"(r0), "=r"(r1), "=r"(r2), "=r"(r3) : "r"(addr))

// int8 IMMA: m16n8k32, s8 x s8 -> s32
#define IMMA16832(d0, d1, d2, d3, a0, a1, a2, a3, b0, b1)                     \
    asm volatile("mma.sync.aligned.m16n8k32.row.col.s32.s8.s8.s32 "           \
                 "{%0,%1,%2,%3}, {%4,%5,%6,%7}, {%8,%9}, {%0,%1,%2,%3};"      \
                 : "+r"(d0), "+r"(d1), "+r"(d2), "+r"(d3)                     \
                 : "r"(a0), "r"(a1), "r"(a2), "r"(a3), "r"(b0), "r"(b1))

// ---------------------------------------------------------------------------
// Prep kernels
// ---------------------------------------------------------------------------
__global__ void prep_A_kernel(const float* __restrict__ samples) {
    size_t idx = (size_t)blockIdx.x * blockDim.x + threadIdx.x;
    if (idx >= (size_t)B_ * KPK) return;
    int r = (int)(idx / KPK), f = (int)(idx % KPK);
    int v = 0;
    if (f < KSEG) {
        v = __float2int_rn(254.0f * (samples[(size_t)r * F_ + f] - 0.5f));
        v = max(-127, min(127, v));
    }
    g_Asp[idx] = (signed char)v;
}

__global__ void prep_B_kernel(const float* __restrict__ bhv) {
    size_t idx = (size_t)blockIdx.x * blockDim.x + threadIdx.x;
    if (idx >= (size_t)NPAD * KPK) return;
    int r = (int)(idx / KPK), f = (int)(idx % KPK);
    int v = 0;
    if (r < D_ && f < KSEG) {
        v = __float2int_rn(127.0f * bhv[(size_t)r * F_ + f]);
        v = max(-127, min(127, v));
    }
    g_Bsp[idx] = (signed char)v;
}

__global__ void pack_centroids_kernel(const float* __restrict__ cent) {
    int idx = blockIdx.x * blockDim.x + threadIdx.x;
    if (idx >= C_ * NW) return;
    int c = idx / NW, w = idx % NW, d0 = w * 32;
    unsigned word = 0u;
    #pragma unroll
    for (int b = 0; b < 32; b++) {
        int d = d0 + b;
        if (d < D_ && cent[(size_t)c * D_ + d] > 0.5f) word |= (1u << b);
    }
    g_centPacked[idx] = word;
}

__global__ void zero_out_kernel(float* __restrict__ out) {
    int i = blockIdx.x * blockDim.x + threadIdx.x;
    if (i < B_ * C_) out[i] = 0.0f;
}

// ---------------------------------------------------------------------------
// Main kernel: int8 mma.sync GEMM (M=128, N=256 per CTA, K=800) with fused
// sign-binarize / XOR-popcount / per-class Hamming epilogue.
// 16 warps: warpM = wid/4 (4 x 32 rows), warpN = wid%4 (4 x 64 cols).
// ---------------------------------------------------------------------------
__global__ void __launch_bounds__(THREADS, 1)
hdc_mma_kernel(float* __restrict__ out) {
    extern __shared__ char smem[];
    const uint32_t sbase = smem_u32(smem);
    const int tid   = threadIdx.x;
    const int wid   = tid >> 5;
    const int lane  = tid & 31;
    const int warpM = wid >> 2;
    const int warpN = wid & 3;
    const int bm = blockIdx.y * TM;
    const int bn = blockIdx.x * TN;

    const char* Abase = (const char*)(g_Asp + (size_t)bm * KPK);
    const char* Bbase = (const char*)(g_Bsp + (size_t)bn * KPK);

    int acc[2][8][4];
    #pragma unroll
    for (int i = 0; i < 2; i++)
        #pragma unroll
        for (int j = 0; j < 8; j++)
            #pragma unroll
            for (int e = 0; e < 4; e++)
                acc[i][j][e] = 0;

    // ---- cp.async chunk loader: 768 x 16B granules (384 rows x 2 halves) ----
    auto load_chunk = [&](int c, int s) {
        uint32_t stage = sbase + s * STAGE_BYTES;
        #pragma unroll
        for (int i = 0; i < 2; i++) {
            int g = tid + THREADS * i;         // 0..1023
            if (g < 768) {
                int row = g >> 1, h = g & 1;
                if (row < A_ROWS) {
                    CP_ASYNC16(stage + row * RSB + h * 16,
                               Abase + (size_t)row * KPK + c * BK + h * 16);
                } else {
                    int r2 = row - A_ROWS;
                    CP_ASYNC16(stage + A_ROWS * RSB + r2 * RSB + h * 16,
                               Bbase + (size_t)r2 * KPK + c * BK + h * 16);
                }
            }
        }
    };

    // ---- prologue: fill STAGES-1 stages ----
    #pragma unroll
    for (int p = 0; p < STAGES - 1; p++) {
        load_chunk(p, p);
        CP_COMMIT();
    }

    // ldmatrix address components (byte-coincident with s8-k32 MMA fragments):
    // A x4: lanes 0-7 rows 0-7 half0, 8-15 rows 8-15 half0,
    //       16-23 rows 0-7 half1, 24-31 rows 8-15 half1.
    // B x4: lanes 0-7 rows 0-7 half0, 8-15 rows 0-7 half1,
    //       16-23 rows 8-15 half0, 24-31 rows 8-15 half1.
    const uint32_t aRowSel = (lane & 15);
    const uint32_t aOff16  = (lane >> 4) * 16;
    const uint32_t bRowSel = ((lane >> 4) << 3) + (lane & 7);
    const uint32_t bOff16  = ((lane >> 3) & 1) * 16;

    for (int c = 0; c < NCHUNK; c++) {
        int s = c % STAGES;
        if (c + 1 < NCHUNK) CP_WAIT1(); else CP_WAIT0();
        __syncthreads();

        int cn = c + STAGES - 1;
        if (cn < NCHUNK) {
            load_chunk(cn, cn % STAGES);
            CP_COMMIT();
        }

        uint32_t sA = sbase + s * STAGE_BYTES + (warpM * 32) * RSB;
        uint32_t sB = sbase + s * STAGE_BYTES + A_ROWS * RSB + (warpN * 64) * RSB;

        uint32_t a[2][4];
        #pragma unroll
        for (int i = 0; i < 2; i++) {
            uint32_t addr = sA + (i * 16 + aRowSel) * RSB + aOff16;
            LDMATRIX_X4(a[i][0], a[i][1], a[i][2], a[i][3], addr);
        }
        uint32_t b[4][4];
        #pragma unroll
        for (int jj = 0; jj < 4; jj++) {
            uint32_t addr = sB + (jj * 16 + bRowSel) * RSB + bOff16;
            LDMATRIX_X4(b[jj][0], b[jj][1], b[jj][2], b[jj][3], addr);
        }
        #pragma unroll
        for (int i = 0; i < 2; i++)
            #pragma unroll
            for (int jj = 0; jj < 4; jj++) {
                IMMA16832(acc[i][2*jj][0], acc[i][2*jj][1], acc[i][2*jj][2], acc[i][2*jj][3],
                          a[i][0], a[i][1], a[i][2], a[i][3], b[jj][0], b[jj][1]);
                IMMA16832(acc[i][2*jj+1][0], acc[i][2*jj+1][1], acc[i][2*jj+1][2], acc[i][2*jj+1][3],
                          a[i][0], a[i][1], a[i][2], a[i][3], b[jj][2], b[jj][3]);
            }
    }

    // =======================================================================
    // Epilogue (fragment layout of s32 C identical to f32 C)
    // =======================================================================
    __syncthreads();   // stage buffers free -> reuse as sign board (128x256 bytes)

    // Phase 1: dump sign bytes. signs[row][col] at smem offset row*256+col.
    {
        int rbase = warpM * 32 + (lane >> 2);
        int cbase = warpN * 64 + ((lane & 3) << 1);
        #pragma unroll
        for (int i = 0; i < 2; i++)
            #pragma unroll
            for (int j = 0; j < 8; j++)
                #pragma unroll
                for (int e = 0; e < 4; e++) {
                    int row = rbase + i * 16 + ((e >> 1) << 3);
                    int col = cbase + j * 8 + (e & 1);
                    smem[row * 256 + col] = (acc[i][j][e] > 0) ? 1 : 0;
                }
    }
    __syncthreads();

    // Phase 2: pack 32 sign bytes -> word, XOR-popcount vs packed centroids.
    {
        int row = tid >> 2;
        int cnt[C_];
        #pragma unroll
        for (int c = 0; c < C_; c++) cnt[c] = 0;

        #pragma unroll
        for (int q = 0; q < 2; q++) {
            int w = ((tid & 3) << 1) + q;
            const uint32_t* p = (const uint32_t*)(smem + row * 256 + w * 32);
            unsigned word = 0u;
            #pragma unroll
            for (int x = 0; x < 8; x++) {
                unsigned nib = ((p[x] & 0x01010101u) * 0x01020408u) >> 24;
                word |= (nib & 0xFu) << (4 * x);
            }
            int dw = (bn >> 5) + w;
            if (dw < NW) {
                #pragma unroll
                for (int c = 0; c < C_; c++)
                    cnt[c] += __popc(word ^ g_centPacked[c * NW + dw]);
            }
        }
        #pragma unroll
        for (int c = 0; c < C_; c++) {
            cnt[c] += __shfl_xor_sync(0xFFFFFFFFu, cnt[c], 1);
            cnt[c] += __shfl_xor_sync(0xFFFFFFFFu, cnt[c], 2);
        }
        if ((lane & 3) == 0) {
            #pragma unroll
            for (int c = 0; c < C_; c++)
                atomicAdd(&out[(size_t)(bm + row) * C_ + c], -(float)cnt[c]);
        }
    }
}

// ---------------------------------------------------------------------------
extern "C" void kernel_launch(void* const* d_in, const int* in_sizes, int n_in,
                              void* d_out, int out_size) {
    const float* samples = (const float*)d_in[0];   // [4096, 784]
    const float* bhv     = (const float*)d_in[1];   // [10000, 784]
    const float* cent    = (const float*)d_in[2];   // [10, 10000]
    float* out = (float*)d_out;                     // [4096, 10]

    cudaFuncSetAttribute(hdc_mma_kernel,
                         cudaFuncAttributeMaxDynamicSharedMemorySize, SMEM_BYTES);

    {
        size_t n = (size_t)B_ * KPK;
        prep_A_kernel<<<(unsigned)((n + 255) / 256), 256>>>(samples);
    }
    {
        size_t n = (size_t)NPAD * KPK;
        prep_B_kernel<<<(unsigned)((n + 255) / 256), 256>>>(bhv);
    }
    pack_centroids_kernel<<<(C_ * NW + 255) / 256, 256>>>(cent);
    zero_out_kernel<<<(B_ * C_ + 255) / 256, 256>>>(out);

    dim3 grid(NPAD / TN, B_ / TM);   // (40, 32)
    hdc_mma_kernel<<<grid, THREADS, SMEM_BYTES>>>(out);
}

// round 11
// speedup vs baseline: 2.0486x; 1.1585x over previous
#include <cuda_runtime.h>
#include <cstdint>

// ---------------------------------------------------------------------------
// Problem constants
// ---------------------------------------------------------------------------
#define B_    4096
#define F_    784
#define D_    10000
#define C_    10
#define NW    313            // ceil(D/32) packed centroid words per class

// Single int8 GEMM: A = round(254*(x-0.5)) [B_, 832], B = round(127*w) [NPAD, 832].
// s32 accumulate exact; rel_err measured 8.39e-4 (frozen quantization scheme).
#define KPK   832            // 13 * 64, zeros in [784, 832)
#define KSEG  784
#define NPAD  10240          // 40 * 256

// Tiling
#define TM      128
#define TN      256
#define BK      64           // int8 elems (bytes) per K-chunk
#define NCHUNK  (KPK / BK)   // 13
#define THREADS 512
#define STAGES  3

// Padded smem rows: 64B data + 16B pad = 80B.
// Row offsets mod 128B = {0,80,32,112,64,16,96,48}: 8 distinct 16B lanes
// covering all 32 banks -> ldmatrix conflict-free (geometry proven rounds 3-7).
#define RSB         80
#define A_ROWS      TM
#define BROWS       TN
#define STAGE_BYTES ((A_ROWS + BROWS) * RSB)     // 30720
#define SMEM_BYTES  (STAGES * STAGE_BYTES)       // 92160 (sign board 32KB fits)

// ---------------------------------------------------------------------------
// Device scratch (allocation-free: __device__ globals)
// ---------------------------------------------------------------------------
__device__ unsigned g_centPacked[C_ * NW];
__device__ __align__(16) signed char g_Asp[(size_t)B_ * KPK];     // 3.4 MB
__device__ __align__(16) signed char g_Bsp[(size_t)NPAD * KPK];   // 8.5 MB

// ---------------------------------------------------------------------------
// PTX helpers (sm_100 baseline: cp.async + ldmatrix + mma.sync only)
// ---------------------------------------------------------------------------
__device__ __forceinline__ uint32_t smem_u32(const void* p) {
    uint32_t a;
    asm("{ .reg .u64 t; cvta.to.shared.u64 t, %1; cvt.u32.u64 %0, t; }"
        : "=r"(a) : "l"(p));
    return a;
}

#define CP_ASYNC16(dst, src) \
    asm volatile("cp.async.cg.shared.global [%0], [%1], 16;" \
                 :: "r"(dst), "l"(src) : "memory")
#define CP_COMMIT() asm volatile("cp.async.commit_group;" ::: "memory")
#define CP_WAIT1()  asm volatile("cp.async.wait_group 1;" ::: "memory")
#define CP_WAIT0()  asm volatile("cp.async.wait_group 0;" ::: "memory")

#define LDMATRIX_X4(r0, r1, r2, r3, addr)                                     \
    asm volatile("ldmatrix.sync.aligned.m8n8.x4.shared.b16 {%0,%1,%2,%3}, [%4];" \
                 : "=r"(r0), "=r"(r1), "=r"(r2), "=r"(r3) : "r"(addr))

// int8 IMMA: m16n8k32, s8 x s8 -> s32
#define IMMA16832(d0, d1, d2, d3, a0, a1, a2, a3, b0, b1)                     \
    asm volatile("mma.sync.aligned.m16n8k32.row.col.s32.s8.s8.s32 "           \
                 "{%0,%1,%2,%3}, {%4,%5,%6,%7}, {%8,%9}, {%0,%1,%2,%3};"      \
                 : "+r"(d0), "+r"(d1), "+r"(d2), "+r"(d3)                     \
                 : "r"(a0), "r"(a1), "r"(a2), "r"(a3), "r"(b0), "r"(b1))

// ---------------------------------------------------------------------------
// Prep kernels (vectorized: float4 load -> char4 store, 4 elems/thread)
// ---------------------------------------------------------------------------
__global__ void prep_A_kernel(const float* __restrict__ samples) {
    size_t idx = (size_t)blockIdx.x * blockDim.x + threadIdx.x;   // quad index
    if (idx >= (size_t)B_ * (KPK / 4)) return;
    int r = (int)(idx / (KPK / 4)), q = (int)(idx % (KPK / 4));
    int f = q * 4;
    char4 o = make_char4(0, 0, 0, 0);
    if (f < KSEG) {
        float4 v = *reinterpret_cast<const float4*>(&samples[(size_t)r * F_ + f]);
        o.x = (signed char)max(-127, min(127, __float2int_rn(254.0f * (v.x - 0.5f))));
        o.y = (signed char)max(-127, min(127, __float2int_rn(254.0f * (v.y - 0.5f))));
        o.z = (signed char)max(-127, min(127, __float2int_rn(254.0f * (v.z - 0.5f))));
        o.w = (signed char)max(-127, min(127, __float2int_rn(254.0f * (v.w - 0.5f))));
    }
    *reinterpret_cast<char4*>(&g_Asp[(size_t)r * KPK + f]) = o;
}

__global__ void prep_B_kernel(const float* __restrict__ bhv) {
    size_t idx = (size_t)blockIdx.x * blockDim.x + threadIdx.x;   // quad index
    if (idx >= (size_t)NPAD * (KPK / 4)) return;
    int r = (int)(idx / (KPK / 4)), q = (int)(idx % (KPK / 4));
    int f = q * 4;
    char4 o = make_char4(0, 0, 0, 0);
    if (r < D_ && f < KSEG) {
        float4 v = *reinterpret_cast<const float4*>(&bhv[(size_t)r * F_ + f]);
        o.x = (signed char)max(-127, min(127, __float2int_rn(127.0f * v.x)));
        o.y = (signed char)max(-127, min(127, __float2int_rn(127.0f * v.y)));
        o.z = (signed char)max(-127, min(127, __float2int_rn(127.0f * v.z)));
        o.w = (signed char)max(-127, min(127, __float2int_rn(127.0f * v.w)));
    }
    *reinterpret_cast<char4*>(&g_Bsp[(size_t)r * KPK + f]) = o;
}

// Fused: pack centroids (idx < C_*NW) AND zero out (idx < B_*C_) in one launch.
__global__ void pack_and_zero_kernel(const float* __restrict__ cent,
                                     float* __restrict__ out) {
    int idx = blockIdx.x * blockDim.x + threadIdx.x;
    if (idx < C_ * NW) {
        int c = idx / NW, w = idx % NW, d0 = w * 32;
        unsigned word = 0u;
        #pragma unroll
        for (int b = 0; b < 32; b++) {
            int d = d0 + b;
            if (d < D_ && cent[(size_t)c * D_ + d] > 0.5f) word |= (1u << b);
        }
        g_centPacked[idx] = word;
    }
    if (idx < B_ * C_) out[idx] = 0.0f;
}

// ---------------------------------------------------------------------------
// Main kernel: int8 mma.sync GEMM (M=128, N=256 per CTA, K=832) with fused
// sign-binarize / XOR-popcount / per-class Hamming epilogue.
// 16 warps: warpM = wid/4 (4 x 32 rows), warpN = wid%4 (4 x 64 cols).
// ---------------------------------------------------------------------------
__global__ void __launch_bounds__(THREADS, 1)
hdc_mma_kernel(float* __restrict__ out) {
    extern __shared__ char smem[];
    const uint32_t sbase = smem_u32(smem);
    const int tid   = threadIdx.x;
    const int wid   = tid >> 5;
    const int lane  = tid & 31;
    const int warpM = wid >> 2;
    const int warpN = wid & 3;
    const int bm = blockIdx.y * TM;
    const int bn = blockIdx.x * TN;

    const char* Abase = (const char*)(g_Asp + (size_t)bm * KPK);
    const char* Bbase = (const char*)(g_Bsp + (size_t)bn * KPK);

    int acc[2][8][4];
    #pragma unroll
    for (int i = 0; i < 2; i++)
        #pragma unroll
        for (int j = 0; j < 8; j++)
            #pragma unroll
            for (int e = 0; e < 4; e++)
                acc[i][j][e] = 0;

    // ---- cp.async chunk loader: 1536 x 16B granules (384 rows x 4 segs) ----
    auto load_chunk = [&](int c, int s) {
        uint32_t stage = sbase + s * STAGE_BYTES;
        #pragma unroll
        for (int i = 0; i < 3; i++) {
            int g   = tid + THREADS * i;       // 0..1535
            int row = g >> 2;
            int seg = g & 3;
            if (row < A_ROWS) {
                CP_ASYNC16(stage + row * RSB + seg * 16,
                           Abase + (size_t)row * KPK + c * BK + seg * 16);
            } else {
                int r2 = row - A_ROWS;
                CP_ASYNC16(stage + A_ROWS * RSB + r2 * RSB + seg * 16,
                           Bbase + (size_t)r2 * KPK + c * BK + seg * 16);
            }
        }
    };

    // ---- prologue: fill STAGES-1 stages ----
    #pragma unroll
    for (int p = 0; p < STAGES - 1; p++) {
        load_chunk(p, p);
        CP_COMMIT();
    }

    // ldmatrix address components (byte-coincident with s8-k32 MMA fragments)
    const uint32_t aRowSel = (lane & 15);
    const uint32_t aOff16  = (lane >> 4) * 16;
    const uint32_t bRowSel = ((lane >> 4) << 3) + (lane & 7);
    const uint32_t bOff16  = ((lane >> 3) & 1) * 16;

    for (int c = 0; c < NCHUNK; c++) {
        int s = c % STAGES;
        if (c + 1 < NCHUNK) CP_WAIT1(); else CP_WAIT0();
        __syncthreads();

        int cn = c + STAGES - 1;
        if (cn < NCHUNK) {
            load_chunk(cn, cn % STAGES);
            CP_COMMIT();
        }

        uint32_t sA = sbase + s * STAGE_BYTES + (warpM * 32) * RSB;
        uint32_t sB = sbase + s * STAGE_BYTES + A_ROWS * RSB + (warpN * 64) * RSB;

        #pragma unroll
        for (int ks = 0; ks < 2; ks++) {       // two k32 halves of the 64B chunk
            uint32_t a[2][4];
            #pragma unroll
            for (int i = 0; i < 2; i++) {
                uint32_t addr = sA + (i * 16 + aRowSel) * RSB + ks * 32 + aOff16;
                LDMATRIX_X4(a[i][0], a[i][1], a[i][2], a[i][3], addr);
            }
            uint32_t b[4][4];
            #pragma unroll
            for (int jj = 0; jj < 4; jj++) {
                uint32_t addr = sB + (jj * 16 + bRowSel) * RSB + ks * 32 + bOff16;
                LDMATRIX_X4(b[jj][0], b[jj][1], b[jj][2], b[jj][3], addr);
            }
            #pragma unroll
            for (int i = 0; i < 2; i++)
                #pragma unroll
                for (int jj = 0; jj < 4; jj++) {
                    IMMA16832(acc[i][2*jj][0], acc[i][2*jj][1], acc[i][2*jj][2], acc[i][2*jj][3],
                              a[i][0], a[i][1], a[i][2], a[i][3], b[jj][0], b[jj][1]);
                    IMMA16832(acc[i][2*jj+1][0], acc[i][2*jj+1][1], acc[i][2*jj+1][2], acc[i][2*jj+1][3],
                              a[i][0], a[i][1], a[i][2], a[i][3], b[jj][2], b[jj][3]);
                }
        }
    }

    // =======================================================================
    // Epilogue (fragment layout of s32 C identical to f32 C)
    // =======================================================================
    __syncthreads();   // stage buffers free -> reuse as sign board (128x256 bytes)

    // Phase 1: dump sign bytes. signs[row][col] at smem offset row*256+col.
    {
        int rbase = warpM * 32 + (lane >> 2);
        int cbase = warpN * 64 + ((lane & 3) << 1);
        #pragma unroll
        for (int i = 0; i < 2; i++)
            #pragma unroll
            for (int j = 0; j < 8; j++)
                #pragma unroll
                for (int e = 0; e < 4; e++) {
                    int row = rbase + i * 16 + ((e >> 1) << 3);
                    int col = cbase + j * 8 + (e & 1);
                    smem[row * 256 + col] = (acc[i][j][e] > 0) ? 1 : 0;
                }
    }
    __syncthreads();

    // Phase 2: pack 32 sign bytes -> word, XOR-popcount vs packed centroids.
    {
        int row = tid >> 2;
        int cnt[C_];
        #pragma unroll
        for (int c = 0; c < C_; c++) cnt[c] = 0;

        #pragma unroll
        for (int q = 0; q < 2; q++) {
            int w = ((tid & 3) << 1) + q;
            const uint32_t* p = (const uint32_t*)(smem + row * 256 + w * 32);
            unsigned word = 0u;
            #pragma unroll
            for (int x = 0; x < 8; x++) {
                unsigned nib = ((p[x] & 0x01010101u) * 0x01020408u) >> 24;
                word |= (nib & 0xFu) << (4 * x);
            }
            int dw = (bn >> 5) + w;
            if (dw < NW) {
                #pragma unroll
                for (int c = 0; c < C_; c++)
                    cnt[c] += __popc(word ^ g_centPacked[c * NW + dw]);
            }
        }
        #pragma unroll
        for (int c = 0; c < C_; c++) {
            cnt[c] += __shfl_xor_sync(0xFFFFFFFFu, cnt[c], 1);
            cnt[c] += __shfl_xor_sync(0xFFFFFFFFu, cnt[c], 2);
        }
        if ((lane & 3) == 0) {
            #pragma unroll
            for (int c = 0; c < C_; c++)
                atomicAdd(&out[(size_t)(bm + row) * C_ + c], -(float)cnt[c]);
        }
    }
}

// ---------------------------------------------------------------------------
extern "C" void kernel_launch(void* const* d_in, const int* in_sizes, int n_in,
                              void* d_out, int out_size) {
    const float* samples = (const float*)d_in[0];   // [4096, 784]
    const float* bhv     = (const float*)d_in[1];   // [10000, 784]
    const float* cent    = (const float*)d_in[2];   // [10, 10000]
    float* out = (float*)d_out;                     // [4096, 10]

    cudaFuncSetAttribute(hdc_mma_kernel,
                         cudaFuncAttributeMaxDynamicSharedMemorySize, SMEM_BYTES);

    {
        size_t n = (size_t)B_ * (KPK / 4);
        prep_A_kernel<<<(unsigned)((n + 255) / 256), 256>>>(samples);
    }
    {
        size_t n = (size_t)NPAD * (KPK / 4);
        prep_B_kernel<<<(unsigned)((n + 255) / 256), 256>>>(bhv);
    }
    pack_and_zero_kernel<<<(B_ * C_ + 255) / 256, 256>>>(cent, out);

    dim3 grid(NPAD / TN, B_ / TM);   // (40, 32)
    hdc_mma_kernel<<<grid, THREADS, SMEM_BYTES>>>(out);
}